// round 3
// baseline (speedup 1.0000x reference)
#include <cuda_runtime.h>
#include <cuda_bf16.h>

#define U_NUM 100000
#define I_NUM 50000
#define NN (U_NUM + I_NUM)
#define D 64
#define NE (NN * D)            // 9,600,000 floats per buffer

// scratch (device globals — no dynamic allocation allowed)
// NOTE: these are ONLY referenced from device code. Taking their address in
// host code yields the host shadow symbol (the R1 bug).
__device__ float g_ego[NE];
__device__ float g_temp[NE];
__device__ float g_acct[NE];
__device__ float g_acce[NE];
__device__ float g_sum[NE];

// ---------------------------------------------------------------------------
// init: ego = concat(user, item); sum = ego
// ---------------------------------------------------------------------------
__global__ void init_k(const float* __restrict__ u, const float* __restrict__ it) {
    int i = blockIdx.x * blockDim.x + threadIdx.x;   // float4 index
    const int n4 = NE / 4;
    if (i >= n4) return;
    const int un4 = U_NUM * D / 4;
    float4 v = (i < un4) ? ((const float4*)u)[i] : ((const float4*)it)[i - un4];
    ((float4*)g_ego)[i] = v;
    ((float4*)g_sum)[i] = v;
}

// ---------------------------------------------------------------------------
// zero the two scatter accumulators
// ---------------------------------------------------------------------------
__global__ void zero_k() {
    int i = blockIdx.x * blockDim.x + threadIdx.x;
    const int n4 = NE / 4;
    if (i >= n4) return;
    float4 z = make_float4(0.f, 0.f, 0.f, 0.f);
    ((float4*)g_acct)[i] = z;
    ((float4*)g_acce)[i] = z;
}

// ---------------------------------------------------------------------------
// dense GEMM: g_temp[N,64] = g_ego[N,64] @ w[64,64]   (w cached in smem)
// 256 threads/block, 64 rows/block, 4 threads per row (16 cols each)
// Globals referenced directly (NOT passed from host).
// ---------------------------------------------------------------------------
__global__ void gemm_k(const float* __restrict__ w) {
    __shared__ float ws[64 * 64];
    const int tid = threadIdx.x;
#pragma unroll
    for (int i = 0; i < 4; i++)
        ((float4*)ws)[tid + i * 256] = ((const float4*)w)[tid + i * 256];
    __syncthreads();

    const int row = blockIdx.x * 64 + (tid >> 2);
    const int cg  = (tid & 3) * 16;
    if (row >= NN) return;

    float acc[16];
#pragma unroll
    for (int j = 0; j < 16; j++) acc[j] = 0.f;

    const float4* xr = (const float4*)(g_ego + (size_t)row * D);
#pragma unroll
    for (int k4 = 0; k4 < 16; k4++) {
        float4 xv = xr[k4];
#pragma unroll
        for (int q = 0; q < 4; q++) {
            float xs = (q == 0) ? xv.x : (q == 1) ? xv.y : (q == 2) ? xv.z : xv.w;
            const float4* wr = (const float4*)(ws + (k4 * 4 + q) * 64 + cg);
            float4 w0 = wr[0], w1 = wr[1], w2v = wr[2], w3 = wr[3];
            acc[0]  += xs * w0.x;  acc[1]  += xs * w0.y;
            acc[2]  += xs * w0.z;  acc[3]  += xs * w0.w;
            acc[4]  += xs * w1.x;  acc[5]  += xs * w1.y;
            acc[6]  += xs * w1.z;  acc[7]  += xs * w1.w;
            acc[8]  += xs * w2v.x; acc[9]  += xs * w2v.y;
            acc[10] += xs * w2v.z; acc[11] += xs * w2v.w;
            acc[12] += xs * w3.x;  acc[13] += xs * w3.y;
            acc[14] += xs * w3.z;  acc[15] += xs * w3.w;
        }
    }
    float4* yr = (float4*)(g_temp + (size_t)row * D + cg);
    yr[0] = make_float4(acc[0],  acc[1],  acc[2],  acc[3]);
    yr[1] = make_float4(acc[4],  acc[5],  acc[6],  acc[7]);
    yr[2] = make_float4(acc[8],  acc[9],  acc[10], acc[11]);
    yr[3] = make_float4(acc[12], acc[13], acc[14], acc[15]);
}

// ---------------------------------------------------------------------------
// fused dual SpMM: for each edge e:
//   acct[rows[e]] += vals[e] * temp[cols[e]]
//   acce[rows[e]] += vals[e] * ego [cols[e]]
// 16 threads per edge, one float4 per thread, vector RED (no return)
// ---------------------------------------------------------------------------
__device__ __forceinline__ void red4(float* p, float x, float y, float z, float w) {
    asm volatile("red.global.add.v4.f32 [%0], {%1,%2,%3,%4};"
                 :: "l"(p), "f"(x), "f"(y), "f"(z), "f"(w) : "memory");
}

__global__ void spmm_k(const int* __restrict__ rows, const int* __restrict__ cols,
                       const float* __restrict__ vals, int nnz) {
    const int t = blockIdx.x * blockDim.x + threadIdx.x;
    const int e = t >> 4;
    if (e >= nnz) return;
    const int part = (t & 15) * 4;

    const int r = __ldg(rows + e);
    const int c = __ldg(cols + e);
    const float v = __ldg(vals + e);

    const float4 tv = *(const float4*)(g_temp + (size_t)c * D + part);
    const float4 ev = *(const float4*)(g_ego  + (size_t)c * D + part);

    red4(g_acct + (size_t)r * D + part, v * tv.x, v * tv.y, v * tv.z, v * tv.w);
    red4(g_acce + (size_t)r * D + part, v * ev.x, v * ev.y, v * ev.z, v * ev.w);
}

// ---------------------------------------------------------------------------
// combine: z = acce * ego; y = z @ w2; ego = lrelu(acct + temp + y);
//          sum += ego; if last: out = sum * 0.25
// ---------------------------------------------------------------------------
__global__ void combine_k(const float* __restrict__ w2, float* __restrict__ out,
                          int last) {
    __shared__ float ws[64 * 64];
    __shared__ float zs[64 * 68];            // stride 68: float4-aligned, no bank conflict
    const int tid = threadIdx.x;
#pragma unroll
    for (int i = 0; i < 4; i++)
        ((float4*)ws)[tid + i * 256] = ((const float4*)w2)[tid + i * 256];

    const int lrow = tid >> 2;
    const int cg   = (tid & 3) * 16;
    const int row  = blockIdx.x * 64 + lrow;
    const int crow = (row < NN) ? row : (NN - 1);
    const size_t base = (size_t)crow * D;

    // z for my 16 columns -> smem
#pragma unroll
    for (int i = 0; i < 4; i++) {
        float4 ev = *(const float4*)(g_ego  + base + cg + i * 4);
        float4 av = *(const float4*)(g_acce + base + cg + i * 4);
        float4 z  = make_float4(av.x * ev.x, av.y * ev.y, av.z * ev.z, av.w * ev.w);
        *(float4*)(zs + lrow * 68 + cg + i * 4) = z;
    }
    __syncthreads();

    float acc[16];
#pragma unroll
    for (int j = 0; j < 16; j++) acc[j] = 0.f;

    const float* zr = zs + lrow * 68;
#pragma unroll
    for (int k4 = 0; k4 < 16; k4++) {
        float4 zv = *(const float4*)(zr + k4 * 4);
#pragma unroll
        for (int q = 0; q < 4; q++) {
            float zk = (q == 0) ? zv.x : (q == 1) ? zv.y : (q == 2) ? zv.z : zv.w;
            const float4* wr = (const float4*)(ws + (k4 * 4 + q) * 64 + cg);
            float4 w0 = wr[0], w1 = wr[1], w2v = wr[2], w3 = wr[3];
            acc[0]  += zk * w0.x;  acc[1]  += zk * w0.y;
            acc[2]  += zk * w0.z;  acc[3]  += zk * w0.w;
            acc[4]  += zk * w1.x;  acc[5]  += zk * w1.y;
            acc[6]  += zk * w1.z;  acc[7]  += zk * w1.w;
            acc[8]  += zk * w2v.x; acc[9]  += zk * w2v.y;
            acc[10] += zk * w2v.z; acc[11] += zk * w2v.w;
            acc[12] += zk * w3.x;  acc[13] += zk * w3.y;
            acc[14] += zk * w3.z;  acc[15] += zk * w3.w;
        }
    }

    if (row >= NN) return;
#pragma unroll
    for (int i = 0; i < 4; i++) {
        float4 at = *(const float4*)(g_acct + base + cg + i * 4);
        float4 tp = *(const float4*)(g_temp + base + cg + i * 4);
        float4 e;
        e.x = at.x + tp.x + acc[i * 4 + 0];
        e.y = at.y + tp.y + acc[i * 4 + 1];
        e.z = at.z + tp.z + acc[i * 4 + 2];
        e.w = at.w + tp.w + acc[i * 4 + 3];
        // leaky_relu, slope 0.01
        e.x = (e.x > 0.f) ? e.x : 0.01f * e.x;
        e.y = (e.y > 0.f) ? e.y : 0.01f * e.y;
        e.z = (e.z > 0.f) ? e.z : 0.01f * e.z;
        e.w = (e.w > 0.f) ? e.w : 0.01f * e.w;
        *(float4*)(g_ego + base + cg + i * 4) = e;

        float4 s = *(const float4*)(g_sum + base + cg + i * 4);
        s.x += e.x; s.y += e.y; s.z += e.z; s.w += e.w;
        *(float4*)(g_sum + base + cg + i * 4) = s;
        if (last) {
            float4 o = make_float4(s.x * 0.25f, s.y * 0.25f, s.z * 0.25f, s.w * 0.25f);
            *(float4*)(out + base + cg + i * 4) = o;
        }
    }
}

// ---------------------------------------------------------------------------
extern "C" void kernel_launch(void* const* d_in, const int* in_sizes, int n_in,
                              void* d_out, int out_size) {
    const float* user = (const float*)d_in[0];
    const float* item = (const float*)d_in[1];
    const float* w1   = (const float*)d_in[2];   // [3,64,64]
    const float* w2   = (const float*)d_in[3];   // [3,64,64]
    const float* vals = (const float*)d_in[4];
    const int*   rows = (const int*)d_in[5];
    const int*   cols = (const int*)d_in[6];
    float* out = (float*)d_out;
    const int nnz = in_sizes[4];

    const int n4 = NE / 4;
    const int gb_elem = (n4 + 255) / 256;
    const int gb_rows = (NN + 63) / 64;
    const int gb_spmm = (nnz * 16 + 255) / 256;

    init_k<<<gb_elem, 256>>>(user, item);

    for (int k = 0; k < 3; k++) {
        zero_k<<<gb_elem, 256>>>();
        gemm_k<<<gb_rows, 256>>>(w1 + k * 64 * 64);
        spmm_k<<<gb_spmm, 256>>>(rows, cols, vals, nnz);
        combine_k<<<gb_rows, 256>>>(w2 + k * 64 * 64, out, (k == 2) ? 1 : 0);
    }
}

// round 6
// speedup vs baseline: 1.3185x; 1.3185x over previous
#include <cuda_runtime.h>
#include <cuda_bf16.h>

#define U_NUM 100000
#define I_NUM 50000
#define NN (U_NUM + I_NUM)
#define D 64
#define NE (NN * D)            // 9,600,000 floats per buffer

// scratch (device globals; only referenced from device code)
__device__ float g_ego[NE];
__device__ float g_agg[NE];
__device__ float g_sum[NE];

// ---------------------------------------------------------------------------
// init: ego = concat(user, item); sum = ego
// ---------------------------------------------------------------------------
__global__ void init_k(const float* __restrict__ u, const float* __restrict__ it) {
    int i = blockIdx.x * blockDim.x + threadIdx.x;   // float4 index
    const int n4 = NE / 4;
    if (i >= n4) return;
    const int un4 = U_NUM * D / 4;
    float4 v = (i < un4) ? ((const float4*)u)[i] : ((const float4*)it)[i - un4];
    ((float4*)g_ego)[i] = v;
    ((float4*)g_sum)[i] = v;
}

// ---------------------------------------------------------------------------
// zero the scatter accumulator
// ---------------------------------------------------------------------------
__global__ void zero_k() {
    int i = blockIdx.x * blockDim.x + threadIdx.x;
    const int n4 = NE / 4;
    if (i >= n4) return;
    ((float4*)g_agg)[i] = make_float4(0.f, 0.f, 0.f, 0.f);
}

// ---------------------------------------------------------------------------
// single SpMM: agg[rows[e]] += vals[e] * ego[cols[e]]
// 16 threads per edge, one float4 per thread, vector RED (no return)
// ---------------------------------------------------------------------------
__device__ __forceinline__ void red4(float* p, float x, float y, float z, float w) {
    asm volatile("red.global.add.v4.f32 [%0], {%1,%2,%3,%4};"
                 :: "l"(p), "f"(x), "f"(y), "f"(z), "f"(w) : "memory");
}

__global__ void spmm_k(const int* __restrict__ rows, const int* __restrict__ cols,
                       const float* __restrict__ vals, int nnz) {
    const int t = blockIdx.x * blockDim.x + threadIdx.x;
    const int e = t >> 4;
    if (e >= nnz) return;
    const int part = (t & 15) * 4;

    const int r = __ldg(rows + e);
    const int c = __ldg(cols + e);
    const float v = __ldg(vals + e);

    const float4 ev = *(const float4*)(g_ego + (size_t)c * D + part);
    red4(g_agg + (size_t)r * D + part, v * ev.x, v * ev.y, v * ev.z, v * ev.w);
}

// ---------------------------------------------------------------------------
// combine:  ego = lrelu((agg + ego) @ w1 + (agg * ego) @ w2)
//           sum += ego; if last: out = sum * 0.25
// 64 rows/block, 4 threads/row (16 output cols each), both weights in smem.
// ---------------------------------------------------------------------------
__global__ void combine_k(const float* __restrict__ w1, const float* __restrict__ w2,
                          float* __restrict__ out, int last) {
    __shared__ float w1s[64 * 64];
    __shared__ float w2s[64 * 64];
    const int tid = threadIdx.x;
#pragma unroll
    for (int i = 0; i < 4; i++) {
        ((float4*)w1s)[tid + i * 256] = ((const float4*)w1)[tid + i * 256];
        ((float4*)w2s)[tid + i * 256] = ((const float4*)w2)[tid + i * 256];
    }
    __syncthreads();

    const int row = blockIdx.x * 64 + (tid >> 2);
    const int cg  = (tid & 3) * 16;
    if (row >= NN) return;
    const size_t base = (size_t)row * D;

    float acc[16];
#pragma unroll
    for (int j = 0; j < 16; j++) acc[j] = 0.f;

    const float4* ar = (const float4*)(g_agg + base);
    const float4* er = (const float4*)(g_ego + base);

#pragma unroll
    for (int k4 = 0; k4 < 16; k4++) {
        float4 a4 = ar[k4];
        float4 e4 = er[k4];
        float sv[4], zv[4];
        sv[0] = a4.x + e4.x; zv[0] = a4.x * e4.x;
        sv[1] = a4.y + e4.y; zv[1] = a4.y * e4.y;
        sv[2] = a4.z + e4.z; zv[2] = a4.z * e4.z;
        sv[3] = a4.w + e4.w; zv[3] = a4.w * e4.w;
#pragma unroll
        for (int q = 0; q < 4; q++) {
            const float s = sv[q];
            const float z = zv[q];
            const float4* w1r = (const float4*)(w1s + (k4 * 4 + q) * 64 + cg);
            const float4* w2r = (const float4*)(w2s + (k4 * 4 + q) * 64 + cg);
            float4 a0 = w1r[0], a1 = w1r[1], a2 = w1r[2], a3 = w1r[3];
            float4 b0 = w2r[0], b1 = w2r[1], b2 = w2r[2], b3 = w2r[3];
            acc[0]  += s * a0.x + z * b0.x;  acc[1]  += s * a0.y + z * b0.y;
            acc[2]  += s * a0.z + z * b0.z;  acc[3]  += s * a0.w + z * b0.w;
            acc[4]  += s * a1.x + z * b1.x;  acc[5]  += s * a1.y + z * b1.y;
            acc[6]  += s * a1.z + z * b1.z;  acc[7]  += s * a1.w + z * b1.w;
            acc[8]  += s * a2.x + z * b2.x;  acc[9]  += s * a2.y + z * b2.y;
            acc[10] += s * a2.z + z * b2.z;  acc[11] += s * a2.w + z * b2.w;
            acc[12] += s * a3.x + z * b3.x;  acc[13] += s * a3.y + z * b3.y;
            acc[14] += s * a3.z + z * b3.z;  acc[15] += s * a3.w + z * b3.w;
        }
    }

#pragma unroll
    for (int i = 0; i < 4; i++) {
        float4 e;
        e.x = acc[i * 4 + 0];
        e.y = acc[i * 4 + 1];
        e.z = acc[i * 4 + 2];
        e.w = acc[i * 4 + 3];
        // leaky_relu, slope 0.01
        e.x = (e.x > 0.f) ? e.x : 0.01f * e.x;
        e.y = (e.y > 0.f) ? e.y : 0.01f * e.y;
        e.z = (e.z > 0.f) ? e.z : 0.01f * e.z;
        e.w = (e.w > 0.f) ? e.w : 0.01f * e.w;
        *(float4*)(g_ego + base + cg + i * 4) = e;

        float4 s = *(const float4*)(g_sum + base + cg + i * 4);
        s.x += e.x; s.y += e.y; s.z += e.z; s.w += e.w;
        *(float4*)(g_sum + base + cg + i * 4) = s;
        if (last) {
            *(float4*)(out + base + cg + i * 4) =
                make_float4(s.x * 0.25f, s.y * 0.25f, s.z * 0.25f, s.w * 0.25f);
        }
    }
}

// ---------------------------------------------------------------------------
extern "C" void kernel_launch(void* const* d_in, const int* in_sizes, int n_in,
                              void* d_out, int out_size) {
    const float* user = (const float*)d_in[0];
    const float* item = (const float*)d_in[1];
    const float* w1   = (const float*)d_in[2];   // [3,64,64]
    const float* w2   = (const float*)d_in[3];   // [3,64,64]
    const float* vals = (const float*)d_in[4];
    const int*   rows = (const int*)d_in[5];
    const int*   cols = (const int*)d_in[6];
    float* out = (float*)d_out;
    const int nnz = in_sizes[4];

    const int n4 = NE / 4;
    const int gb_elem = (n4 + 255) / 256;
    const int gb_rows = (NN + 63) / 64;
    const int gb_spmm = (nnz * 16 + 255) / 256;

    init_k<<<gb_elem, 256>>>(user, item);

    for (int k = 0; k < 3; k++) {
        zero_k<<<gb_elem, 256>>>();
        spmm_k<<<gb_spmm, 256>>>(rows, cols, vals, nnz);
        combine_k<<<gb_rows, 256>>>(w1 + k * 64 * 64, w2 + k * 64 * 64, out,
                                    (k == 2) ? 1 : 0);
    }
}

// round 8
// speedup vs baseline: 2.1796x; 1.6531x over previous
#include <cuda_runtime.h>
#include <cuda_bf16.h>

#define U_NUM 100000
#define I_NUM 50000
#define NN (U_NUM + I_NUM)
#define D 64
#define NE (NN * D)            // 9,600,000 floats per buffer

// scratch (device globals; only referenced from device code)
__device__ float g_ego[NE];
__device__ float g_agg[NE];
__device__ float g_sum[NE];

// ---------------------------------------------------------------------------
// init: ego = concat(user, item); sum = ego; agg = 0 (for layer 0's spmm)
// ---------------------------------------------------------------------------
__global__ void init_k(const float* __restrict__ u, const float* __restrict__ it) {
    int i = blockIdx.x * blockDim.x + threadIdx.x;   // float4 index
    const int n4 = NE / 4;
    if (i >= n4) return;
    const int un4 = U_NUM * D / 4;
    float4 v = (i < un4) ? ((const float4*)u)[i] : ((const float4*)it)[i - un4];
    ((float4*)g_ego)[i] = v;
    ((float4*)g_sum)[i] = v;
    ((float4*)g_agg)[i] = make_float4(0.f, 0.f, 0.f, 0.f);
}

// ---------------------------------------------------------------------------
// single SpMM: agg[rows[e]] += vals[e] * ego[cols[e]]
// 16 threads per edge, one float4 per thread, vector RED (no return)
// ---------------------------------------------------------------------------
__device__ __forceinline__ void red4(float* p, float x, float y, float z, float w) {
    asm volatile("red.global.add.v4.f32 [%0], {%1,%2,%3,%4};"
                 :: "l"(p), "f"(x), "f"(y), "f"(z), "f"(w) : "memory");
}

__global__ void spmm_k(const int* __restrict__ rows, const int* __restrict__ cols,
                       const float* __restrict__ vals, int nnz) {
    const int t = blockIdx.x * blockDim.x + threadIdx.x;
    const int e = t >> 4;
    if (e >= nnz) return;
    const int part = (t & 15) * 4;

    const int r = __ldg(rows + e);
    const int c = __ldg(cols + e);
    const float v = __ldg(vals + e);

    const float4 ev = *(const float4*)(g_ego + (size_t)c * D + part);
    red4(g_agg + (size_t)r * D + part, v * ev.x, v * ev.y, v * ev.z, v * ev.w);
}

// ---------------------------------------------------------------------------
// combine:  ego = lrelu((agg + ego) @ w1 + (agg * ego) @ w2)
//           sum += ego; agg = 0 (ready for next layer); if last: out = sum/4
// Register row-blocking: 256 threads, each thread owns 4 rows x 16 cols.
// Weight values fetched from smem are reused across 4 rows -> 4:1 FMA:LDS.
// ---------------------------------------------------------------------------
__device__ __forceinline__ float comp4(const float4& v, int q) {
    return (q == 0) ? v.x : (q == 1) ? v.y : (q == 2) ? v.z : v.w;
}

__global__ __launch_bounds__(256, 1)
void combine_k(const float* __restrict__ w1, const float* __restrict__ w2,
               float* __restrict__ out, int last) {
    __shared__ float w1s[64 * 64];
    __shared__ float w2s[64 * 64];
    const int tid = threadIdx.x;
#pragma unroll
    for (int i = 0; i < 4; i++) {
        ((float4*)w1s)[tid + i * 256] = ((const float4*)w1)[tid + i * 256];
        ((float4*)w2s)[tid + i * 256] = ((const float4*)w2)[tid + i * 256];
    }
    __syncthreads();

    const int lrow = tid >> 2;            // 0..63
    const int cg   = (tid & 3) * 16;      // output col group
    const int r0   = (blockIdx.x * 64 + lrow) * 4;   // 4 consecutive rows

    float acc[4][16];
#pragma unroll
    for (int j = 0; j < 4; j++)
#pragma unroll
        for (int c = 0; c < 16; c++) acc[j][c] = 0.f;

#pragma unroll 4
    for (int k4 = 0; k4 < 16; k4++) {
        float4 a[4], e[4];
#pragma unroll
        for (int j = 0; j < 4; j++) {
            const int r = r0 + j;
            if (r < NN) {
                a[j] = *(const float4*)(g_agg + (size_t)r * D + k4 * 4);
                e[j] = *(const float4*)(g_ego + (size_t)r * D + k4 * 4);
            } else {
                a[j] = make_float4(0.f, 0.f, 0.f, 0.f);
                e[j] = make_float4(0.f, 0.f, 0.f, 0.f);
            }
        }
#pragma unroll
        for (int q = 0; q < 4; q++) {
            const float4* w1r = (const float4*)(w1s + (k4 * 4 + q) * 64 + cg);
            const float4* w2r = (const float4*)(w2s + (k4 * 4 + q) * 64 + cg);
            float4 A0 = w1r[0], A1 = w1r[1], A2 = w1r[2], A3 = w1r[3];
            float4 B0 = w2r[0], B1 = w2r[1], B2 = w2r[2], B3 = w2r[3];
#pragma unroll
            for (int j = 0; j < 4; j++) {
                const float av = comp4(a[j], q);
                const float ev = comp4(e[j], q);
                const float s = av + ev;
                const float z = av * ev;
                acc[j][0]  += s * A0.x + z * B0.x;
                acc[j][1]  += s * A0.y + z * B0.y;
                acc[j][2]  += s * A0.z + z * B0.z;
                acc[j][3]  += s * A0.w + z * B0.w;
                acc[j][4]  += s * A1.x + z * B1.x;
                acc[j][5]  += s * A1.y + z * B1.y;
                acc[j][6]  += s * A1.z + z * B1.z;
                acc[j][7]  += s * A1.w + z * B1.w;
                acc[j][8]  += s * A2.x + z * B2.x;
                acc[j][9]  += s * A2.y + z * B2.y;
                acc[j][10] += s * A2.z + z * B2.z;
                acc[j][11] += s * A2.w + z * B2.w;
                acc[j][12] += s * A3.x + z * B3.x;
                acc[j][13] += s * A3.y + z * B3.y;
                acc[j][14] += s * A3.z + z * B3.z;
                acc[j][15] += s * A3.w + z * B3.w;
            }
        }
    }

    // epilogue: lrelu, ego update, sum update, agg zero, optional out
#pragma unroll
    for (int j = 0; j < 4; j++) {
        const int r = r0 + j;
        if (r >= NN) break;
        const size_t base = (size_t)r * D + cg;
#pragma unroll
        for (int i = 0; i < 4; i++) {
            float4 e;
            e.x = acc[j][i * 4 + 0];
            e.y = acc[j][i * 4 + 1];
            e.z = acc[j][i * 4 + 2];
            e.w = acc[j][i * 4 + 3];
            e.x = (e.x > 0.f) ? e.x : 0.01f * e.x;
            e.y = (e.y > 0.f) ? e.y : 0.01f * e.y;
            e.z = (e.z > 0.f) ? e.z : 0.01f * e.z;
            e.w = (e.w > 0.f) ? e.w : 0.01f * e.w;
            *(float4*)(g_ego + base + i * 4) = e;

            float4 s = *(const float4*)(g_sum + base + i * 4);
            s.x += e.x; s.y += e.y; s.z += e.z; s.w += e.w;
            *(float4*)(g_sum + base + i * 4) = s;

            *(float4*)(g_agg + base + i * 4) = make_float4(0.f, 0.f, 0.f, 0.f);

            if (last) {
                *(float4*)(out + base + i * 4) =
                    make_float4(s.x * 0.25f, s.y * 0.25f, s.z * 0.25f, s.w * 0.25f);
            }
        }
    }
}

// ---------------------------------------------------------------------------
extern "C" void kernel_launch(void* const* d_in, const int* in_sizes, int n_in,
                              void* d_out, int out_size) {
    const float* user = (const float*)d_in[0];
    const float* item = (const float*)d_in[1];
    const float* w1   = (const float*)d_in[2];   // [3,64,64]
    const float* w2   = (const float*)d_in[3];   // [3,64,64]
    const float* vals = (const float*)d_in[4];
    const int*   rows = (const int*)d_in[5];
    const int*   cols = (const int*)d_in[6];
    float* out = (float*)d_out;
    const int nnz = in_sizes[4];

    const int n4 = NE / 4;
    const int gb_elem = (n4 + 255) / 256;
    const int gb_comb = (NN + 255) / 256;            // 64 row-groups x 4 rows
    const int gb_spmm = (nnz * 16 + 255) / 256;

    init_k<<<gb_elem, 256>>>(user, item);

    for (int k = 0; k < 3; k++) {
        spmm_k<<<gb_spmm, 256>>>(rows, cols, vals, nnz);
        combine_k<<<gb_comb, 256>>>(w1 + k * 64 * 64, w2 + k * 64 * 64, out,
                                    (k == 2) ? 1 : 0);
    }
}

// round 9
// speedup vs baseline: 3.0169x; 1.3842x over previous
#include <cuda_runtime.h>
#include <cuda_bf16.h>

#define U_NUM 100000
#define I_NUM 50000
#define NN (U_NUM + I_NUM)
#define D 64
#define NE (NN * D)              // 9,600,000 floats per buffer
#define NNZ_MAX 2400000
#define SCAN_NB ((NN + 255) / 256)   // 586 blocks

// scratch (device globals; only referenced from device code)
__device__ float g_ego[NE];
__device__ float g_agg[NE];
__device__ float g_sum[NE];
__device__ int   g_cnt[NN];          // per-row degree
__device__ int   g_rowptr[NN + 1];   // CSR row pointers
__device__ int   g_cursor[NN];       // scatter cursors
__device__ int2  g_cv[NNZ_MAX];      // (col, val bits) row-sorted
__device__ int   g_blksum[1024];     // scan partials

// ---------------------------------------------------------------------------
// init: ego = concat(user, item); sum = ego; cnt = 0
// ---------------------------------------------------------------------------
__global__ void init_k(const float* __restrict__ u, const float* __restrict__ it) {
    int i = blockIdx.x * blockDim.x + threadIdx.x;   // float4 index
    const int n4 = NE / 4;
    if (i < NN) g_cnt[i] = 0;
    if (i >= n4) return;
    const int un4 = U_NUM * D / 4;
    float4 v = (i < un4) ? ((const float4*)u)[i] : ((const float4*)it)[i - un4];
    ((float4*)g_ego)[i] = v;
    ((float4*)g_sum)[i] = v;
}

// ---------------------------------------------------------------------------
// CSR build: histogram -> exclusive scan (3 kernels) -> scatter
// ---------------------------------------------------------------------------
__global__ void hist_k(const int* __restrict__ rows, int nnz) {
    int e = blockIdx.x * blockDim.x + threadIdx.x;
    if (e < nnz) atomicAdd(&g_cnt[rows[e]], 1);
}

__global__ void scan1_k() {   // per-block exclusive scan of g_cnt -> g_rowptr
    __shared__ int s[256];
    const int t = threadIdx.x;
    const int idx = blockIdx.x * 256 + t;
    int x = (idx < NN) ? g_cnt[idx] : 0;
    s[t] = x;
    __syncthreads();
#pragma unroll
    for (int off = 1; off < 256; off <<= 1) {
        int y = (t >= off) ? s[t - off] : 0;
        __syncthreads();
        s[t] += y;
        __syncthreads();
    }
    if (idx < NN) g_rowptr[idx] = s[t] - x;        // exclusive
    if (t == 255) g_blksum[blockIdx.x] = s[255];   // block total
}

__global__ void scan2_k() {   // single-block exclusive scan of block sums
    __shared__ int s[1024];
    const int t = threadIdx.x;
    int x = (t < SCAN_NB) ? g_blksum[t] : 0;
    s[t] = x;
    __syncthreads();
#pragma unroll
    for (int off = 1; off < 1024; off <<= 1) {
        int y = (t >= off) ? s[t - off] : 0;
        __syncthreads();
        s[t] += y;
        __syncthreads();
    }
    if (t < SCAN_NB) g_blksum[t] = s[t] - x;       // exclusive
}

__global__ void scan3_k(int nnz) {   // add block offsets; init cursors
    const int idx = blockIdx.x * 256 + threadIdx.x;
    if (idx < NN) {
        int v = g_rowptr[idx] + g_blksum[blockIdx.x];
        g_rowptr[idx] = v;
        g_cursor[idx] = v;
    }
    if (idx == 0) g_rowptr[NN] = nnz;
}

__global__ void scatter_k(const int* __restrict__ rows, const int* __restrict__ cols,
                          const float* __restrict__ vals, int nnz) {
    int e = blockIdx.x * blockDim.x + threadIdx.x;
    if (e >= nnz) return;
    const int r = rows[e];
    const int pos = atomicAdd(&g_cursor[r], 1);
    g_cv[pos] = make_int2(cols[e], __float_as_int(vals[e]));
}

// ---------------------------------------------------------------------------
// CSR SpMM: agg[n] = sum_{edges of n} val * ego[col]   (no atomics, no zeroing)
// 16 threads per node, each owns one float4 chunk, register accumulate.
// ---------------------------------------------------------------------------
__global__ void spmm_csr_k() {
    const int t = blockIdx.x * blockDim.x + threadIdx.x;
    const int node = t >> 4;
    if (node >= NN) return;
    const int part = (t & 15) * 4;

    const int beg = __ldg(&g_rowptr[node]);
    const int end = __ldg(&g_rowptr[node + 1]);

    float4 acc = make_float4(0.f, 0.f, 0.f, 0.f);
    int i = beg;
    // 2-deep software pipeline for MLP
    for (; i + 2 <= end; i += 2) {
        int2 cv0 = __ldg(&g_cv[i]);
        int2 cv1 = __ldg(&g_cv[i + 1]);
        float4 e0 = *(const float4*)(g_ego + (size_t)cv0.x * D + part);
        float4 e1 = *(const float4*)(g_ego + (size_t)cv1.x * D + part);
        float v0 = __int_as_float(cv0.y);
        float v1 = __int_as_float(cv1.y);
        acc.x += v0 * e0.x; acc.y += v0 * e0.y; acc.z += v0 * e0.z; acc.w += v0 * e0.w;
        acc.x += v1 * e1.x; acc.y += v1 * e1.y; acc.z += v1 * e1.z; acc.w += v1 * e1.w;
    }
    if (i < end) {
        int2 cv = __ldg(&g_cv[i]);
        float4 e = *(const float4*)(g_ego + (size_t)cv.x * D + part);
        float v = __int_as_float(cv.y);
        acc.x += v * e.x; acc.y += v * e.y; acc.z += v * e.z; acc.w += v * e.w;
    }
    *(float4*)(g_agg + (size_t)node * D + part) = acc;
}

// ---------------------------------------------------------------------------
// combine:  ego = lrelu((agg + ego) @ w1 + (agg * ego) @ w2)
//           sum += ego; if last: out = sum * 0.25
// Register row-blocking: each thread owns 4 rows x 16 cols (4:1 FMA:LDS).
// ---------------------------------------------------------------------------
__device__ __forceinline__ float comp4(const float4& v, int q) {
    return (q == 0) ? v.x : (q == 1) ? v.y : (q == 2) ? v.z : v.w;
}

__global__ __launch_bounds__(256, 1)
void combine_k(const float* __restrict__ w1, const float* __restrict__ w2,
               float* __restrict__ out, int last) {
    __shared__ float w1s[64 * 64];
    __shared__ float w2s[64 * 64];
    const int tid = threadIdx.x;
#pragma unroll
    for (int i = 0; i < 4; i++) {
        ((float4*)w1s)[tid + i * 256] = ((const float4*)w1)[tid + i * 256];
        ((float4*)w2s)[tid + i * 256] = ((const float4*)w2)[tid + i * 256];
    }
    __syncthreads();

    const int lrow = tid >> 2;            // 0..63
    const int cg   = (tid & 3) * 16;      // output col group
    const int r0   = (blockIdx.x * 64 + lrow) * 4;   // 4 consecutive rows

    float acc[4][16];
#pragma unroll
    for (int j = 0; j < 4; j++)
#pragma unroll
        for (int c = 0; c < 16; c++) acc[j][c] = 0.f;

#pragma unroll 4
    for (int k4 = 0; k4 < 16; k4++) {
        float4 a[4], e[4];
#pragma unroll
        for (int j = 0; j < 4; j++) {
            const int r = r0 + j;
            if (r < NN) {
                a[j] = *(const float4*)(g_agg + (size_t)r * D + k4 * 4);
                e[j] = *(const float4*)(g_ego + (size_t)r * D + k4 * 4);
            } else {
                a[j] = make_float4(0.f, 0.f, 0.f, 0.f);
                e[j] = make_float4(0.f, 0.f, 0.f, 0.f);
            }
        }
#pragma unroll
        for (int q = 0; q < 4; q++) {
            const float4* w1r = (const float4*)(w1s + (k4 * 4 + q) * 64 + cg);
            const float4* w2r = (const float4*)(w2s + (k4 * 4 + q) * 64 + cg);
            float4 A0 = w1r[0], A1 = w1r[1], A2 = w1r[2], A3 = w1r[3];
            float4 B0 = w2r[0], B1 = w2r[1], B2 = w2r[2], B3 = w2r[3];
#pragma unroll
            for (int j = 0; j < 4; j++) {
                const float av = comp4(a[j], q);
                const float ev = comp4(e[j], q);
                const float s = av + ev;
                const float z = av * ev;
                acc[j][0]  += s * A0.x + z * B0.x;
                acc[j][1]  += s * A0.y + z * B0.y;
                acc[j][2]  += s * A0.z + z * B0.z;
                acc[j][3]  += s * A0.w + z * B0.w;
                acc[j][4]  += s * A1.x + z * B1.x;
                acc[j][5]  += s * A1.y + z * B1.y;
                acc[j][6]  += s * A1.z + z * B1.z;
                acc[j][7]  += s * A1.w + z * B1.w;
                acc[j][8]  += s * A2.x + z * B2.x;
                acc[j][9]  += s * A2.y + z * B2.y;
                acc[j][10] += s * A2.z + z * B2.z;
                acc[j][11] += s * A2.w + z * B2.w;
                acc[j][12] += s * A3.x + z * B3.x;
                acc[j][13] += s * A3.y + z * B3.y;
                acc[j][14] += s * A3.z + z * B3.z;
                acc[j][15] += s * A3.w + z * B3.w;
            }
        }
    }

    // epilogue: lrelu, ego update, sum update, optional out
#pragma unroll
    for (int j = 0; j < 4; j++) {
        const int r = r0 + j;
        if (r >= NN) break;
        const size_t base = (size_t)r * D + cg;
#pragma unroll
        for (int i = 0; i < 4; i++) {
            float4 e;
            e.x = acc[j][i * 4 + 0];
            e.y = acc[j][i * 4 + 1];
            e.z = acc[j][i * 4 + 2];
            e.w = acc[j][i * 4 + 3];
            e.x = (e.x > 0.f) ? e.x : 0.01f * e.x;
            e.y = (e.y > 0.f) ? e.y : 0.01f * e.y;
            e.z = (e.z > 0.f) ? e.z : 0.01f * e.z;
            e.w = (e.w > 0.f) ? e.w : 0.01f * e.w;
            *(float4*)(g_ego + base + i * 4) = e;

            float4 s = *(const float4*)(g_sum + base + i * 4);
            s.x += e.x; s.y += e.y; s.z += e.z; s.w += e.w;
            *(float4*)(g_sum + base + i * 4) = s;

            if (last) {
                *(float4*)(out + base + i * 4) =
                    make_float4(s.x * 0.25f, s.y * 0.25f, s.z * 0.25f, s.w * 0.25f);
            }
        }
    }
}

// ---------------------------------------------------------------------------
extern "C" void kernel_launch(void* const* d_in, const int* in_sizes, int n_in,
                              void* d_out, int out_size) {
    const float* user = (const float*)d_in[0];
    const float* item = (const float*)d_in[1];
    const float* w1   = (const float*)d_in[2];   // [3,64,64]
    const float* w2   = (const float*)d_in[3];   // [3,64,64]
    const float* vals = (const float*)d_in[4];
    const int*   rows = (const int*)d_in[5];
    const int*   cols = (const int*)d_in[6];
    float* out = (float*)d_out;
    const int nnz = in_sizes[4];

    const int n4 = NE / 4;
    const int gb_elem = (n4 + 255) / 256;
    const int gb_edge = (nnz + 255) / 256;
    const int gb_comb = (NN + 255) / 256;
    const int gb_node = (NN * 16 + 255) / 256;

    init_k<<<gb_elem, 256>>>(user, item);

    // CSR build (amortized over 3 layers)
    hist_k<<<gb_edge, 256>>>(rows, nnz);
    scan1_k<<<SCAN_NB, 256>>>();
    scan2_k<<<1, 1024>>>();
    scan3_k<<<SCAN_NB, 256>>>(nnz);
    scatter_k<<<gb_edge, 256>>>(rows, cols, vals, nnz);

    for (int k = 0; k < 3; k++) {
        spmm_csr_k<<<gb_node, 256>>>();
        combine_k<<<gb_comb, 256>>>(w1 + k * 64 * 64, w2 + k * 64 * 64, out,
                                    (k == 2) ? 1 : 0);
    }
}

// round 10
// speedup vs baseline: 3.0724x; 1.0184x over previous
#include <cuda_runtime.h>
#include <cuda_bf16.h>

#define U_NUM 100000
#define I_NUM 50000
#define NN (U_NUM + I_NUM)
#define D 64
#define NE (NN * D)              // 9,600,000 floats per buffer
#define NNZ_MAX 2400000
#define SCAN_NB ((NN + 255) / 256)   // 586 blocks

typedef unsigned long long u64;

// scratch (device globals; only referenced from device code)
__device__ float g_ego[NE];
__device__ float g_agg[NE];
__device__ float g_sum[NE];
__device__ int   g_cnt[NN];          // per-row degree
__device__ int   g_rowptr[NN + 1];   // CSR row pointers
__device__ int   g_cursor[NN];       // scatter cursors
__device__ int2  g_cv[NNZ_MAX];      // (col, val bits) row-sorted
__device__ int   g_blksum[1024];     // scan partials

// ---------------------------------------------------------------------------
// packed f32x2 helpers (FFMA2 is PTX-only; ptxas never auto-fuses)
// ---------------------------------------------------------------------------
__device__ __forceinline__ u64 pack2(float x) {
    u64 r; asm("mov.b64 %0, {%1, %1};" : "=l"(r) : "f"(x)); return r;
}
__device__ __forceinline__ u64 fma2(u64 a, u64 b, u64 c) {
    u64 d; asm("fma.rn.f32x2 %0, %1, %2, %3;" : "=l"(d) : "l"(a), "l"(b), "l"(c));
    return d;
}
__device__ __forceinline__ float2 unpack2(u64 v) {
    float2 f; asm("mov.b64 {%0, %1}, %2;" : "=f"(f.x), "=f"(f.y) : "l"(v));
    return f;
}

// ---------------------------------------------------------------------------
// init: ego = concat(user, item); sum = ego; cnt = 0
// ---------------------------------------------------------------------------
__global__ void init_k(const float* __restrict__ u, const float* __restrict__ it) {
    int i = blockIdx.x * blockDim.x + threadIdx.x;   // float4 index
    const int n4 = NE / 4;
    if (i < NN) g_cnt[i] = 0;
    if (i >= n4) return;
    const int un4 = U_NUM * D / 4;
    float4 v = (i < un4) ? ((const float4*)u)[i] : ((const float4*)it)[i - un4];
    ((float4*)g_ego)[i] = v;
    ((float4*)g_sum)[i] = v;
}

// ---------------------------------------------------------------------------
// CSR build: histogram -> exclusive scan (3 kernels) -> scatter
// ---------------------------------------------------------------------------
__global__ void hist_k(const int* __restrict__ rows, int nnz) {
    int e = blockIdx.x * blockDim.x + threadIdx.x;
    if (e < nnz) atomicAdd(&g_cnt[rows[e]], 1);
}

__global__ void scan1_k() {   // per-block exclusive scan of g_cnt -> g_rowptr
    __shared__ int s[256];
    const int t = threadIdx.x;
    const int idx = blockIdx.x * 256 + t;
    int x = (idx < NN) ? g_cnt[idx] : 0;
    s[t] = x;
    __syncthreads();
#pragma unroll
    for (int off = 1; off < 256; off <<= 1) {
        int y = (t >= off) ? s[t - off] : 0;
        __syncthreads();
        s[t] += y;
        __syncthreads();
    }
    if (idx < NN) g_rowptr[idx] = s[t] - x;        // exclusive
    if (t == 255) g_blksum[blockIdx.x] = s[255];   // block total
}

__global__ void scan2_k() {   // single-block exclusive scan of block sums
    __shared__ int s[1024];
    const int t = threadIdx.x;
    int x = (t < SCAN_NB) ? g_blksum[t] : 0;
    s[t] = x;
    __syncthreads();
#pragma unroll
    for (int off = 1; off < 1024; off <<= 1) {
        int y = (t >= off) ? s[t - off] : 0;
        __syncthreads();
        s[t] += y;
        __syncthreads();
    }
    if (t < SCAN_NB) g_blksum[t] = s[t] - x;       // exclusive
}

__global__ void scan3_k(int nnz) {   // add block offsets; init cursors
    const int idx = blockIdx.x * 256 + threadIdx.x;
    if (idx < NN) {
        int v = g_rowptr[idx] + g_blksum[blockIdx.x];
        g_rowptr[idx] = v;
        g_cursor[idx] = v;
    }
    if (idx == 0) g_rowptr[NN] = nnz;
}

__global__ void scatter_k(const int* __restrict__ rows, const int* __restrict__ cols,
                          const float* __restrict__ vals, int nnz) {
    int e = blockIdx.x * blockDim.x + threadIdx.x;
    if (e >= nnz) return;
    const int r = rows[e];
    const int pos = atomicAdd(&g_cursor[r], 1);
    g_cv[pos] = make_int2(cols[e], __float_as_int(vals[e]));
}

// ---------------------------------------------------------------------------
// CSR SpMM: agg[n] = sum_{edges of n} val * ego[col]   (no atomics, no zeroing)
// 16 threads per node, each owns one float4 chunk, register accumulate.
// ---------------------------------------------------------------------------
__global__ void spmm_csr_k() {
    const int t = blockIdx.x * blockDim.x + threadIdx.x;
    const int node = t >> 4;
    if (node >= NN) return;
    const int part = (t & 15) * 4;

    const int beg = __ldg(&g_rowptr[node]);
    const int end = __ldg(&g_rowptr[node + 1]);

    float4 acc = make_float4(0.f, 0.f, 0.f, 0.f);
    int i = beg;
    for (; i + 2 <= end; i += 2) {
        int2 cv0 = __ldg(&g_cv[i]);
        int2 cv1 = __ldg(&g_cv[i + 1]);
        float4 e0 = *(const float4*)(g_ego + (size_t)cv0.x * D + part);
        float4 e1 = *(const float4*)(g_ego + (size_t)cv1.x * D + part);
        float v0 = __int_as_float(cv0.y);
        float v1 = __int_as_float(cv1.y);
        acc.x += v0 * e0.x; acc.y += v0 * e0.y; acc.z += v0 * e0.z; acc.w += v0 * e0.w;
        acc.x += v1 * e1.x; acc.y += v1 * e1.y; acc.z += v1 * e1.z; acc.w += v1 * e1.w;
    }
    if (i < end) {
        int2 cv = __ldg(&g_cv[i]);
        float4 e = *(const float4*)(g_ego + (size_t)cv.x * D + part);
        float v = __int_as_float(cv.y);
        acc.x += v * e.x; acc.y += v * e.y; acc.z += v * e.z; acc.w += v * e.w;
    }
    *(float4*)(g_agg + (size_t)node * D + part) = acc;
}

// ---------------------------------------------------------------------------
// combine:  ego = lrelu((agg + ego) @ w1 + (agg * ego) @ w2)
//           sum += ego; if last: out = sum * 0.25
// Register row-blocking (4 rows x 16 cols per thread) + packed f32x2 FMA:
// each FFMA2 covers two output columns -> half the FMA instruction stream.
// ---------------------------------------------------------------------------
__device__ __forceinline__ float comp4(const float4& v, int q) {
    return (q == 0) ? v.x : (q == 1) ? v.y : (q == 2) ? v.z : v.w;
}

__global__ __launch_bounds__(256, 1)
void combine_k(const float* __restrict__ w1, const float* __restrict__ w2,
               float* __restrict__ out, int last) {
    __shared__ float w1s[64 * 64];
    __shared__ float w2s[64 * 64];
    const int tid = threadIdx.x;
#pragma unroll
    for (int i = 0; i < 4; i++) {
        ((float4*)w1s)[tid + i * 256] = ((const float4*)w1)[tid + i * 256];
        ((float4*)w2s)[tid + i * 256] = ((const float4*)w2)[tid + i * 256];
    }
    __syncthreads();

    const int lrow = tid >> 2;            // 0..63
    const int cg   = (tid & 3) * 16;      // output col group
    const int r0   = (blockIdx.x * 64 + lrow) * 4;   // 4 consecutive rows

    u64 acc2[4][8];                        // 4 rows x 8 col-pairs
    const u64 z64 = pack2(0.f);
#pragma unroll
    for (int j = 0; j < 4; j++)
#pragma unroll
        for (int p = 0; p < 8; p++) acc2[j][p] = z64;

#pragma unroll 4
    for (int k4 = 0; k4 < 16; k4++) {
        float4 a[4], e[4];
#pragma unroll
        for (int j = 0; j < 4; j++) {
            const int r = r0 + j;
            if (r < NN) {
                a[j] = *(const float4*)(g_agg + (size_t)r * D + k4 * 4);
                e[j] = *(const float4*)(g_ego + (size_t)r * D + k4 * 4);
            } else {
                a[j] = make_float4(0.f, 0.f, 0.f, 0.f);
                e[j] = make_float4(0.f, 0.f, 0.f, 0.f);
            }
        }
#pragma unroll
        for (int q = 0; q < 4; q++) {
            const ulonglong2* w1p = (const ulonglong2*)(w1s + (k4 * 4 + q) * 64 + cg);
            const ulonglong2* w2p = (const ulonglong2*)(w2s + (k4 * 4 + q) * 64 + cg);
            ulonglong2 A0 = w1p[0], A1 = w1p[1], A2 = w1p[2], A3 = w1p[3];
            ulonglong2 B0 = w2p[0], B1 = w2p[1], B2 = w2p[2], B3 = w2p[3];
#pragma unroll
            for (int j = 0; j < 4; j++) {
                const float av = comp4(a[j], q);
                const float ev = comp4(e[j], q);
                const u64 s2 = pack2(av + ev);
                const u64 zz = pack2(av * ev);
                acc2[j][0] = fma2(s2, A0.x, acc2[j][0]);
                acc2[j][0] = fma2(zz, B0.x, acc2[j][0]);
                acc2[j][1] = fma2(s2, A0.y, acc2[j][1]);
                acc2[j][1] = fma2(zz, B0.y, acc2[j][1]);
                acc2[j][2] = fma2(s2, A1.x, acc2[j][2]);
                acc2[j][2] = fma2(zz, B1.x, acc2[j][2]);
                acc2[j][3] = fma2(s2, A1.y, acc2[j][3]);
                acc2[j][3] = fma2(zz, B1.y, acc2[j][3]);
                acc2[j][4] = fma2(s2, A2.x, acc2[j][4]);
                acc2[j][4] = fma2(zz, B2.x, acc2[j][4]);
                acc2[j][5] = fma2(s2, A2.y, acc2[j][5]);
                acc2[j][5] = fma2(zz, B2.y, acc2[j][5]);
                acc2[j][6] = fma2(s2, A3.x, acc2[j][6]);
                acc2[j][6] = fma2(zz, B3.x, acc2[j][6]);
                acc2[j][7] = fma2(s2, A3.y, acc2[j][7]);
                acc2[j][7] = fma2(zz, B3.y, acc2[j][7]);
            }
        }
    }

    // epilogue: lrelu, ego update, sum update, optional out
#pragma unroll
    for (int j = 0; j < 4; j++) {
        const int r = r0 + j;
        if (r >= NN) break;
        const size_t base = (size_t)r * D + cg;
#pragma unroll
        for (int i = 0; i < 4; i++) {
            float2 lo = unpack2(acc2[j][i * 2]);
            float2 hi = unpack2(acc2[j][i * 2 + 1]);
            float4 e;
            e.x = lo.x; e.y = lo.y; e.z = hi.x; e.w = hi.y;
            e.x = (e.x > 0.f) ? e.x : 0.01f * e.x;
            e.y = (e.y > 0.f) ? e.y : 0.01f * e.y;
            e.z = (e.z > 0.f) ? e.z : 0.01f * e.z;
            e.w = (e.w > 0.f) ? e.w : 0.01f * e.w;
            *(float4*)(g_ego + base + i * 4) = e;

            float4 s = *(const float4*)(g_sum + base + i * 4);
            s.x += e.x; s.y += e.y; s.z += e.z; s.w += e.w;
            *(float4*)(g_sum + base + i * 4) = s;

            if (last) {
                *(float4*)(out + base + i * 4) =
                    make_float4(s.x * 0.25f, s.y * 0.25f, s.z * 0.25f, s.w * 0.25f);
            }
        }
    }
}

// ---------------------------------------------------------------------------
extern "C" void kernel_launch(void* const* d_in, const int* in_sizes, int n_in,
                              void* d_out, int out_size) {
    const float* user = (const float*)d_in[0];
    const float* item = (const float*)d_in[1];
    const float* w1   = (const float*)d_in[2];   // [3,64,64]
    const float* w2   = (const float*)d_in[3];   // [3,64,64]
    const float* vals = (const float*)d_in[4];
    const int*   rows = (const int*)d_in[5];
    const int*   cols = (const int*)d_in[6];
    float* out = (float*)d_out;
    const int nnz = in_sizes[4];

    const int n4 = NE / 4;
    const int gb_elem = (n4 + 255) / 256;
    const int gb_edge = (nnz + 255) / 256;
    const int gb_comb = (NN + 255) / 256;
    const int gb_node = (NN * 16 + 255) / 256;

    init_k<<<gb_elem, 256>>>(user, item);

    // CSR build (amortized over 3 layers)
    hist_k<<<gb_edge, 256>>>(rows, nnz);
    scan1_k<<<SCAN_NB, 256>>>();
    scan2_k<<<1, 1024>>>();
    scan3_k<<<SCAN_NB, 256>>>(nnz);
    scatter_k<<<gb_edge, 256>>>(rows, cols, vals, nnz);

    for (int k = 0; k < 3; k++) {
        spmm_csr_k<<<gb_node, 256>>>();
        combine_k<<<gb_comb, 256>>>(w1 + k * 64 * 64, w2 + k * 64 * 64, out,
                                    (k == 2) ? 1 : 0);
    }
}